// round 13
// baseline (speedup 1.0000x reference)
#include <cuda_runtime.h>
#include <stdint.h>

constexpr int S_DIM = 16384;
constexpr int T_DIM = 8192;
constexpr int B_DIM = 16;
constexpr int NH    = 16;
constexpr int KEEP  = 24;
constexpr int CAP   = 128;
constexpr int TRIG  = 96;
constexpr unsigned FULLM = 0xFFFFFFFFu;

constexpr size_t OFF_XNEAR = 0;
constexpr size_t OFF_IDIST = (size_t)B_DIM * T_DIM * NH;      // 2097152
constexpr size_t OFF_ILON  = OFF_IDIST + (size_t)T_DIM * NH;  // 2228224
constexpr size_t OFF_ILAT  = OFF_ILON  + (size_t)T_DIM * NH;  // 2359296

__device__ __forceinline__ unsigned saddr(const void* p) {
    return (unsigned)__cvta_generic_to_shared(p);
}
#define CP16(dst_s, src_g) \
    asm volatile("cp.async.cg.shared.global [%0], [%1], 16;" :: "r"(dst_s), "l"(src_g))
#define CPCOMMIT() asm volatile("cp.async.commit_group;" ::: "memory")
#define CPWAIT6()  asm volatile("cp.async.wait_group 6;"  ::: "memory")

// Pack (nonneg float, index): unsigned order == (value asc, index asc),
// exactly jax.lax.top_k's stable order.
__device__ __forceinline__ unsigned long long pack_key(float v, unsigned idx) {
    return ((unsigned long long)__float_as_uint(v) << 32) | idx;
}

__device__ __forceinline__ unsigned long long warp_min64(unsigned long long v) {
    #pragma unroll
    for (int o = 16; o > 0; o >>= 1) {
        unsigned long long w = __shfl_xor_sync(FULLM, v, o);
        if (w < v) v = w;
    }
    return v;
}

// Warp-collective: write `rounds` smallest keys of buf[0..cnt) sorted into
// buf[0..rounds); returns the rounds-th smallest. Keys unique (distinct idx).
__device__ __forceinline__ unsigned long long select_sorted(
    unsigned long long* buf, int cnt, int rounds, int lane)
{
    unsigned long long k[CAP / 32];
    unsigned long long lmin = ~0ull;
    #pragma unroll
    for (int q = 0; q < CAP / 32; q++) {
        int p = lane + 32 * q;
        k[q] = (p < cnt) ? buf[p] : ~0ull;
        if (k[q] < lmin) lmin = k[q];
    }
    unsigned long long g = ~0ull;
    for (int r = 0; r < rounds; r++) {
        g = warp_min64(lmin);
        if (lmin == g) {
            unsigned long long nl = ~0ull;
            #pragma unroll
            for (int q = 0; q < CAP / 32; q++) {
                if (k[q] == g) k[q] = ~0ull;
                if (k[q] < nl) nl = k[q];
            }
            lmin = nl;
        }
        if (lane == 0) buf[r] = g;
    }
    __syncwarp();
    return g;
}

// Append passing lanes; rebuild keeps KEEP best and tightens thr (inclusive).
__device__ __forceinline__ void try_append(bool p, float v, unsigned idx,
    unsigned long long* buf, int& cnt, float& thr, int lane)
{
    unsigned m = __ballot_sync(FULLM, p);
    if (m == 0) return;
    if (p) buf[cnt + __popc(m & ((1u << lane) - 1u))] = pack_key(v, idx);
    cnt += __popc(m);
    if (cnt > TRIG) {
        __syncwarp();
        unsigned long long g = select_sorted(buf, cnt, KEEP, lane);
        cnt = KEEP;
        thr = __uint_as_float((unsigned)(g >> 32));
    }
}

__global__ __launch_bounds__(128)
void nn_topk_kernel(const float* __restrict__ x,
                    const float* __restrict__ dlon,
                    const float* __restrict__ dlat,
                    float* __restrict__ out)
{
    // 4 warps x 8 slots x 1KB (64 float4). Dist warps (0,1): float4[0..31] =
    // 128 dlon elems, float4[32..63] = 128 dlat elems. Abs warps (2,3): slot =
    // 256 contiguous elems of one stream.
    __shared__ float4 ring[4][8][64];
    __shared__ unsigned long long sbuf[4][CAP];

    const int row  = blockIdx.x;
    const int warp = threadIdx.x >> 5;
    const int lane = threadIdx.x & 31;
    unsigned long long* buf = sbuf[warp];

    float thr = __int_as_float(0x7f800000);  // +inf until first rebuild
    int cnt = 0;

    const bool is_dist = (warp < 2);
    const float* pA;
    const float* pB;
    int stride;
    if (is_dist) {         // half-row dist scan: two streams
        pA = dlon + (size_t)row * S_DIM + warp * 8192;
        pB = dlat + (size_t)row * S_DIM + warp * 8192;
        stride = 128;
    } else {               // full-row abs scan: one stream, chunk halves
        pA = (warp == 2 ? dlon : dlat) + (size_t)row * S_DIM;
        pB = pA + 128;
        stride = 256;
    }

    // Prologue: chunks 0..6 into slots 0..6, one commit group each.
    #pragma unroll
    for (int p = 0; p < 7; ++p) {
        CP16(saddr(&ring[warp][p][lane]),      pA + p * stride + lane * 4);
        CP16(saddr(&ring[warp][p][32 + lane]), pB + p * stride + lane * 4);
        CPCOMMIT();
    }
    const float* rA = pA + 7 * stride;   // refill cursor (chunk it+7)
    const float* rB = pB + 7 * stride;

    // Iteration it: read slot it&7; refill chunk it+7 into slot (it+7)&7
    // (== (SLOT+7)&7, one behind the read slot — R9's proven mapping).
    // Group g carries chunk g; wait_group 6 at iter it => groups 0..it done.

    if (is_dist) {
        // ---- euclidean distance, half-row scan on squared values ----
        unsigned base = (unsigned)(warp * 8192) + (unsigned)lane * 4u;
        #define DIST_ITER(SLOT, WSLOT, REFILL)                                 \
        {                                                                      \
            CPWAIT6();                                                         \
            float4 a = ring[warp][SLOT][lane];                                 \
            float4 b = ring[warp][SLOT][32 + lane];                            \
            if (REFILL) {                                                      \
                CP16(saddr(&ring[warp][WSLOT][lane]),      rA + lane * 4);     \
                CP16(saddr(&ring[warp][WSLOT][32 + lane]), rB + lane * 4);     \
                rA += 128; rB += 128;                                          \
            }                                                                  \
            CPCOMMIT();                                                        \
            float s0 = fmaf(a.x, a.x, b.x * b.x);                              \
            float s1 = fmaf(a.y, a.y, b.y * b.y);                              \
            float s2 = fmaf(a.z, a.z, b.z * b.z);                              \
            float s3 = fmaf(a.w, a.w, b.w * b.w);                              \
            float mn = fminf(fminf(s0, s1), fminf(s2, s3));                    \
            if (__any_sync(FULLM, mn <= thr)) {                                \
                try_append(s0 <= thr, s0, base + 0u, buf, cnt, thr, lane);     \
                try_append(s1 <= thr, s1, base + 1u, buf, cnt, thr, lane);     \
                try_append(s2 <= thr, s2, base + 2u, buf, cnt, thr, lane);     \
                try_append(s3 <= thr, s3, base + 3u, buf, cnt, thr, lane);     \
            }                                                                  \
            base += 128;                                                       \
        }
        // Iters 0..55: 7 blocks of 8 (slots compile-time const).
        #pragma unroll 1
        for (int ib = 0; ib < 7; ++ib) {
            DIST_ITER(0, 7, true) DIST_ITER(1, 0, true) DIST_ITER(2, 1, true)
            DIST_ITER(3, 2, true) DIST_ITER(4, 3, true) DIST_ITER(5, 4, true)
            DIST_ITER(6, 5, true) DIST_ITER(7, 6, true)
        }
        // Iter 56 (chunk 63 -> slot 7), then 57..63 drain (empty commits
        // keep group arithmetic uniform).
        DIST_ITER(0, 7, true)
        DIST_ITER(1, 0, false) DIST_ITER(2, 1, false) DIST_ITER(3, 2, false)
        DIST_ITER(4, 3, false) DIST_ITER(5, 4, false) DIST_ITER(6, 5, false)
        DIST_ITER(7, 6, false)
        #undef DIST_ITER

        // Re-key survivors with exact IEEE sqrt; per-half top-16 sorted.
        __syncwarp();
        for (int p = lane; p < cnt; p += 32) {
            unsigned long long e = buf[p];
            float d = __fsqrt_rn(__uint_as_float((unsigned)(e >> 32)));
            buf[p] = pack_key(d, (unsigned)e);
        }
        __syncwarp();
        select_sorted(buf, cnt, NH, lane);               // sbuf[warp][0..15]
    } else {
        // ---- |d_lon| (warp 2) / |d_lat| (warp 3), full-row scan ----
        unsigned base = (unsigned)lane * 4u;
        #define ABS_ITER(SLOT, WSLOT, REFILL)                                  \
        {                                                                      \
            CPWAIT6();                                                         \
            float4 a0 = ring[warp][SLOT][lane];                                \
            float4 a1 = ring[warp][SLOT][32 + lane];                           \
            if (REFILL) {                                                      \
                CP16(saddr(&ring[warp][WSLOT][lane]),      rA + lane * 4);     \
                CP16(saddr(&ring[warp][WSLOT][32 + lane]), rB + lane * 4);     \
                rA += 256; rB += 256;                                          \
            }                                                                  \
            CPCOMMIT();                                                        \
            float m0 = fminf(fminf(fabsf(a0.x), fabsf(a0.y)),                  \
                             fminf(fabsf(a0.z), fabsf(a0.w)));                 \
            float m1 = fminf(fminf(fabsf(a1.x), fabsf(a1.y)),                  \
                             fminf(fabsf(a1.z), fabsf(a1.w)));                 \
            if (__any_sync(FULLM, fminf(m0, m1) <= thr)) {                     \
                float v;                                                       \
                v = fabsf(a0.x); try_append(v <= thr, v, base +   0u, buf, cnt, thr, lane); \
                v = fabsf(a0.y); try_append(v <= thr, v, base +   1u, buf, cnt, thr, lane); \
                v = fabsf(a0.z); try_append(v <= thr, v, base +   2u, buf, cnt, thr, lane); \
                v = fabsf(a0.w); try_append(v <= thr, v, base +   3u, buf, cnt, thr, lane); \
                v = fabsf(a1.x); try_append(v <= thr, v, base + 128u, buf, cnt, thr, lane); \
                v = fabsf(a1.y); try_append(v <= thr, v, base + 129u, buf, cnt, thr, lane); \
                v = fabsf(a1.z); try_append(v <= thr, v, base + 130u, buf, cnt, thr, lane); \
                v = fabsf(a1.w); try_append(v <= thr, v, base + 131u, buf, cnt, thr, lane); \
            }                                                                  \
            base += 256;                                                       \
        }
        #pragma unroll 1
        for (int ib = 0; ib < 7; ++ib) {
            ABS_ITER(0, 7, true) ABS_ITER(1, 0, true) ABS_ITER(2, 1, true)
            ABS_ITER(3, 2, true) ABS_ITER(4, 3, true) ABS_ITER(5, 4, true)
            ABS_ITER(6, 5, true) ABS_ITER(7, 6, true)
        }
        ABS_ITER(0, 7, true)
        ABS_ITER(1, 0, false) ABS_ITER(2, 1, false) ABS_ITER(3, 2, false)
        ABS_ITER(4, 3, false) ABS_ITER(5, 4, false) ABS_ITER(6, 5, false)
        ABS_ITER(7, 6, false)
        #undef ABS_ITER

        __syncwarp();
        select_sorted(buf, cnt, NH, lane);
        const size_t obase = (warp == 2) ? OFF_ILON : OFF_ILAT;
        if (lane < NH) {
            unsigned idx = (unsigned)buf[lane];
            out[obase + (size_t)row * NH + lane] = (float)idx;
        }
    }

    __syncthreads();   // dist halves' top-16 visible to warp 0

    if (warp == 0) {
        // Merge two sorted 16-lists (32 unique keys) -> global top-16.
        unsigned long long k = (lane < NH) ? sbuf[0][lane] : sbuf[1][lane - NH];
        unsigned long long res = 0;
        #pragma unroll
        for (int r = 0; r < NH; ++r) {
            unsigned long long g = warp_min64(k);
            if (k == g) k = ~0ull;
            if (lane == r) res = g;          // lane r holds r-th smallest
        }
        unsigned idx = (unsigned)res;
        if (lane < NH)
            out[OFF_IDIST + (size_t)row * NH + lane] = (float)idx;
        // x_nearest gather: out[b][row][j] = x[b][idx_j]   (e == 1)
        #pragma unroll
        for (int p = lane; p < B_DIM * NH; p += 32) {
            int b = p >> 4;
            int j = p & 15;
            unsigned ij = __shfl_sync(FULLM, idx, j);
            out[OFF_XNEAR + (size_t)b * (T_DIM * NH) + (size_t)row * NH + j] =
                x[(size_t)b * S_DIM + ij];
        }
    }
}

extern "C" void kernel_launch(void* const* d_in, const int* in_sizes, int n_in,
                              void* d_out, int out_size) {
    (void)in_sizes; (void)n_in; (void)out_size;
    const float* x    = (const float*)d_in[0];
    const float* dlon = (const float*)d_in[1];
    const float* dlat = (const float*)d_in[2];
    nn_topk_kernel<<<T_DIM, 128>>>(x, dlon, dlat, (float*)d_out);
}

// round 14
// speedup vs baseline: 5.7324x; 5.7324x over previous
#include <cuda_runtime.h>
#include <stdint.h>

constexpr int S_DIM = 16384;
constexpr int T_DIM = 8192;
constexpr int B_DIM = 16;
constexpr int NH    = 16;
constexpr int KEEP  = 24;
constexpr int CAP   = 128;
constexpr int TRIG  = 96;
constexpr unsigned FULLM = 0xFFFFFFFFu;

constexpr size_t OFF_XNEAR = 0;
constexpr size_t OFF_IDIST = (size_t)B_DIM * T_DIM * NH;      // 2097152
constexpr size_t OFF_ILON  = OFF_IDIST + (size_t)T_DIM * NH;  // 2228224
constexpr size_t OFF_ILAT  = OFF_ILON  + (size_t)T_DIM * NH;  // 2359296

__device__ __forceinline__ unsigned saddr(const void* p) {
    return (unsigned)__cvta_generic_to_shared(p);
}
#define CP16(dst_s, src_g) \
    asm volatile("cp.async.cg.shared.global [%0], [%1], 16;" :: "r"(dst_s), "l"(src_g))
#define CPCOMMIT() asm volatile("cp.async.commit_group;" ::: "memory")
#define CPWAIT6()  asm volatile("cp.async.wait_group 6;"  ::: "memory")

// Pack (nonneg float, index): unsigned order == (value asc, index asc),
// exactly jax.lax.top_k's stable order.
__device__ __forceinline__ unsigned long long pack_key(float v, unsigned idx) {
    return ((unsigned long long)__float_as_uint(v) << 32) | idx;
}

__device__ __forceinline__ unsigned long long warp_min64(unsigned long long v) {
    #pragma unroll
    for (int o = 16; o > 0; o >>= 1) {
        unsigned long long w = __shfl_xor_sync(FULLM, v, o);
        if (w < v) v = w;
    }
    return v;
}

// Warp-collective: write `rounds` smallest keys of buf[0..cnt) sorted into
// buf[0..rounds); returns the rounds-th smallest. Keys unique (distinct idx).
__device__ __forceinline__ unsigned long long select_sorted(
    unsigned long long* buf, int cnt, int rounds, int lane)
{
    unsigned long long k[CAP / 32];
    unsigned long long lmin = ~0ull;
    #pragma unroll
    for (int q = 0; q < CAP / 32; q++) {
        int p = lane + 32 * q;
        k[q] = (p < cnt) ? buf[p] : ~0ull;
        if (k[q] < lmin) lmin = k[q];
    }
    unsigned long long g = ~0ull;
    for (int r = 0; r < rounds; r++) {
        g = warp_min64(lmin);
        if (lmin == g) {
            unsigned long long nl = ~0ull;
            #pragma unroll
            for (int q = 0; q < CAP / 32; q++) {
                if (k[q] == g) k[q] = ~0ull;
                if (k[q] < nl) nl = k[q];
            }
            lmin = nl;
        }
        if (lane == 0) buf[r] = g;
    }
    __syncwarp();
    return g;
}

// Append passing lanes; rebuild keeps KEEP best and tightens thr (inclusive).
__device__ __forceinline__ void try_append(bool p, float v, unsigned idx,
    unsigned long long* buf, int& cnt, float& thr, int lane)
{
    unsigned m = __ballot_sync(FULLM, p);
    if (m == 0) return;
    if (p) buf[cnt + __popc(m & ((1u << lane) - 1u))] = pack_key(v, idx);
    cnt += __popc(m);
    if (cnt > TRIG) {
        __syncwarp();
        unsigned long long g = select_sorted(buf, cnt, KEEP, lane);
        cnt = KEEP;
        thr = __uint_as_float((unsigned)(g >> 32));
    }
}

__global__ __launch_bounds__(128)
void nn_topk_kernel(const float* __restrict__ x,
                    const float* __restrict__ dlon,
                    const float* __restrict__ dlat,
                    float* __restrict__ out)
{
    // 4 warps x 8 slots x 1KB (64 float4). Dist warps (0,1): float4[0..31] =
    // 128 dlon elems, float4[32..63] = 128 dlat elems (half-row each). Abs
    // warps (2,3): slot = 256 contiguous elems of one full row.
    __shared__ float4 ring[4][8][64];
    __shared__ unsigned long long sbuf[4][CAP];

    const int row  = blockIdx.x;
    const int warp = threadIdx.x >> 5;
    const int lane = threadIdx.x & 31;
    unsigned long long* buf = sbuf[warp];

    float thr = __int_as_float(0x7f800000);  // +inf until first rebuild
    int cnt = 0;

    const bool is_dist = (warp < 2);
    const float* pA;
    const float* pB;
    int stride;
    if (is_dist) {         // half-row dist scan: two streams
        pA = dlon + (size_t)row * S_DIM + warp * 8192;
        pB = dlat + (size_t)row * S_DIM + warp * 8192;
        stride = 128;
    } else {               // full-row abs scan: one stream, chunk halves
        pA = (warp == 2 ? dlon : dlat) + (size_t)row * S_DIM;
        pB = pA + 128;
        stride = 256;
    }

    constexpr int NIT = 64;  // every warp: 64 iterations x 1KB

    // Prologue: chunks 0..6 into slots 0..6, one commit group each.
    #pragma unroll
    for (int p = 0; p < 7; ++p) {
        CP16(saddr(&ring[warp][p][lane]),      pA + p * stride + lane * 4);
        CP16(saddr(&ring[warp][p][32 + lane]), pB + p * stride + lane * 4);
        CPCOMMIT();
    }
    const float* rA = pA + 7 * stride;   // refill cursor (chunk it+7)
    const float* rB = pB + 7 * stride;

    // Iteration it: group g carries chunk g; 7+it groups committed at entry;
    // wait_group 6 => groups 0..it complete => chunk it resident in slot it&7.
    // Refill chunk it+7 -> slot (it+7)&7 (last read at iter it-1). R9 mapping.

    if (is_dist) {
        // ---- euclidean distance, half-row scan on squared values ----
        unsigned base = (unsigned)(warp * 8192) + (unsigned)lane * 4u;
        #pragma unroll 1
        for (int it = 0; it < NIT; ++it) {
            CPWAIT6();
            const int s = it & 7;
            float4 a = ring[warp][s][lane];
            float4 b = ring[warp][s][32 + lane];
            if (it < NIT - 7) {
                const int w = (it + 7) & 7;
                CP16(saddr(&ring[warp][w][lane]),      rA + lane * 4);
                CP16(saddr(&ring[warp][w][32 + lane]), rB + lane * 4);
                rA += 128; rB += 128;
            }
            CPCOMMIT();                          // uniform group count
            float s0 = fmaf(a.x, a.x, b.x * b.x);
            float s1 = fmaf(a.y, a.y, b.y * b.y);
            float s2 = fmaf(a.z, a.z, b.z * b.z);
            float s3 = fmaf(a.w, a.w, b.w * b.w);
            float mn = fminf(fminf(s0, s1), fminf(s2, s3));
            if (__any_sync(FULLM, mn <= thr)) {  // rare once thr tightens
                try_append(s0 <= thr, s0, base + 0u, buf, cnt, thr, lane);
                try_append(s1 <= thr, s1, base + 1u, buf, cnt, thr, lane);
                try_append(s2 <= thr, s2, base + 2u, buf, cnt, thr, lane);
                try_append(s3 <= thr, s3, base + 3u, buf, cnt, thr, lane);
            }
            base += 128;
        }
        // Re-key survivors with exact IEEE sqrt; per-half top-16 sorted.
        __syncwarp();
        for (int p = lane; p < cnt; p += 32) {
            unsigned long long e = buf[p];
            float d = __fsqrt_rn(__uint_as_float((unsigned)(e >> 32)));
            buf[p] = pack_key(d, (unsigned)e);
        }
        __syncwarp();
        select_sorted(buf, cnt, NH, lane);       // sbuf[warp][0..15]
    } else {
        // ---- |d_lon| (warp 2) / |d_lat| (warp 3), full-row scan ----
        unsigned base = (unsigned)lane * 4u;
        #pragma unroll 1
        for (int it = 0; it < NIT; ++it) {
            CPWAIT6();
            const int s = it & 7;
            float4 a0 = ring[warp][s][lane];
            float4 a1 = ring[warp][s][32 + lane];
            if (it < NIT - 7) {
                const int w = (it + 7) & 7;
                CP16(saddr(&ring[warp][w][lane]),      rA + lane * 4);
                CP16(saddr(&ring[warp][w][32 + lane]), rB + lane * 4);
                rA += 256; rB += 256;
            }
            CPCOMMIT();
            float m0 = fminf(fminf(fabsf(a0.x), fabsf(a0.y)),
                             fminf(fabsf(a0.z), fabsf(a0.w)));
            float m1 = fminf(fminf(fabsf(a1.x), fabsf(a1.y)),
                             fminf(fabsf(a1.z), fabsf(a1.w)));
            if (__any_sync(FULLM, fminf(m0, m1) <= thr)) {
                float v;
                v = fabsf(a0.x); try_append(v <= thr, v, base +   0u, buf, cnt, thr, lane);
                v = fabsf(a0.y); try_append(v <= thr, v, base +   1u, buf, cnt, thr, lane);
                v = fabsf(a0.z); try_append(v <= thr, v, base +   2u, buf, cnt, thr, lane);
                v = fabsf(a0.w); try_append(v <= thr, v, base +   3u, buf, cnt, thr, lane);
                v = fabsf(a1.x); try_append(v <= thr, v, base + 128u, buf, cnt, thr, lane);
                v = fabsf(a1.y); try_append(v <= thr, v, base + 129u, buf, cnt, thr, lane);
                v = fabsf(a1.z); try_append(v <= thr, v, base + 130u, buf, cnt, thr, lane);
                v = fabsf(a1.w); try_append(v <= thr, v, base + 131u, buf, cnt, thr, lane);
            }
            base += 256;
        }
        __syncwarp();
        select_sorted(buf, cnt, NH, lane);
        const size_t obase = (warp == 2) ? OFF_ILON : OFF_ILAT;
        if (lane < NH) {
            unsigned idx = (unsigned)buf[lane];
            out[obase + (size_t)row * NH + lane] = (float)idx;
        }
    }

    __syncthreads();   // dist halves' top-16 visible to warp 0

    if (warp == 0) {
        // Merge two sorted 16-lists (32 unique keys) -> global top-16.
        unsigned long long k = (lane < NH) ? sbuf[0][lane] : sbuf[1][lane - NH];
        unsigned long long res = 0;
        #pragma unroll
        for (int r = 0; r < NH; ++r) {
            unsigned long long g = warp_min64(k);
            if (k == g) k = ~0ull;
            if (lane == r) res = g;          // lane r holds r-th smallest
        }
        unsigned idx = (unsigned)res;
        if (lane < NH)
            out[OFF_IDIST + (size_t)row * NH + lane] = (float)idx;
        // x_nearest gather: out[b][row][j] = x[b][idx_j]   (e == 1)
        #pragma unroll
        for (int p = lane; p < B_DIM * NH; p += 32) {
            int b = p >> 4;
            int j = p & 15;
            unsigned ij = __shfl_sync(FULLM, idx, j);
            out[OFF_XNEAR + (size_t)b * (T_DIM * NH) + (size_t)row * NH + j] =
                x[(size_t)b * S_DIM + ij];
        }
    }
}

extern "C" void kernel_launch(void* const* d_in, const int* in_sizes, int n_in,
                              void* d_out, int out_size) {
    (void)in_sizes; (void)n_in; (void)out_size;
    const float* x    = (const float*)d_in[0];
    const float* dlon = (const float*)d_in[1];
    const float* dlat = (const float*)d_in[2];
    nn_topk_kernel<<<T_DIM, 128>>>(x, dlon, dlat, (float*)d_out);
}

// round 15
// speedup vs baseline: 22.6849x; 3.9573x over previous
#include <cuda_runtime.h>
#include <stdint.h>

constexpr int S_DIM = 16384;
constexpr int T_DIM = 8192;
constexpr int B_DIM = 16;
constexpr int NH    = 16;
constexpr int KEEP  = 24;
constexpr int CAP   = 224;   // TRIG + 128 (max one-chunk append burst)
constexpr int TRIG  = 96;
constexpr unsigned FULLM = 0xFFFFFFFFu;

constexpr size_t OFF_XNEAR = 0;
constexpr size_t OFF_IDIST = (size_t)B_DIM * T_DIM * NH;      // 2097152
constexpr size_t OFF_ILON  = OFF_IDIST + (size_t)T_DIM * NH;  // 2228224
constexpr size_t OFF_ILAT  = OFF_ILON  + (size_t)T_DIM * NH;  // 2359296

__device__ __forceinline__ unsigned saddr(const void* p) {
    return (unsigned)__cvta_generic_to_shared(p);
}
#define CP16(dst_s, src_g) \
    asm volatile("cp.async.cg.shared.global [%0], [%1], 16;" :: "r"(dst_s), "l"(src_g))
#define CPCOMMIT() asm volatile("cp.async.commit_group;" ::: "memory")
#define CPWAIT6()  asm volatile("cp.async.wait_group 6;"  ::: "memory")

// Pack (nonneg float, index): unsigned order == (value asc, index asc),
// exactly jax.lax.top_k's stable order.
__device__ __forceinline__ unsigned long long pack_key(float v, unsigned idx) {
    return ((unsigned long long)__float_as_uint(v) << 32) | idx;
}

__device__ __forceinline__ unsigned long long warp_min64(unsigned long long v) {
    #pragma unroll
    for (int o = 16; o > 0; o >>= 1) {
        unsigned long long w = __shfl_xor_sync(FULLM, v, o);
        if (w < v) v = w;
    }
    return v;
}

__device__ __forceinline__ float warp_min32(float v) {
    #pragma unroll
    for (int o = 16; o > 0; o >>= 1)
        v = fminf(v, __shfl_xor_sync(FULLM, v, o));
    return v;
}

// Exact warp-collective selection: `rounds` smallest keys of buf[0..cnt)
// written sorted into buf[0..rounds); returns rounds-th smallest.
// Keys unique (distinct low-32 indices). Used for final outputs + fallback.
__device__ __forceinline__ unsigned long long select_sorted(
    unsigned long long* buf, int cnt, int rounds, int lane)
{
    unsigned long long k[CAP / 32];
    unsigned long long lmin = ~0ull;
    #pragma unroll
    for (int q = 0; q < CAP / 32; q++) {
        int p = lane + 32 * q;
        k[q] = (p < cnt) ? buf[p] : ~0ull;
        if (k[q] < lmin) lmin = k[q];
    }
    unsigned long long g = ~0ull;
    #pragma unroll 1
    for (int r = 0; r < rounds; r++) {
        g = warp_min64(lmin);
        if (lmin == g) {
            unsigned long long nl = ~0ull;
            #pragma unroll
            for (int q = 0; q < CAP / 32; q++) {
                if (k[q] == g) k[q] = ~0ull;
                if (k[q] < nl) nl = k[q];
            }
            lmin = nl;
        }
        if (lane == 0) buf[r] = g;
    }
    __syncwarp();
    return g;
}

// Cheap rebuild on 32-bit values: find v >= exact KEEP-th smallest (duplicate
// removal only inflates rank -> inclusive), compact entries <= v to the front.
// Fallback to exact selection if ties leave cnt > TRIG (never on random data).
__device__ __forceinline__ void rebuild32(
    unsigned long long* buf, int& cnt, float& thr, int lane)
{
    const float INF = __int_as_float(0x7f800000);
    float v[CAP / 32];
    float lmin = INF;
    #pragma unroll
    for (int q = 0; q < CAP / 32; q++) {
        int p = lane + 32 * q;
        v[q] = (p < cnt) ? __uint_as_float((unsigned)(buf[p] >> 32)) : INF;
        lmin = fminf(lmin, v[q]);
    }
    float g = INF;
    #pragma unroll 1
    for (int r = 0; r < KEEP; r++) {
        g = warp_min32(lmin);
        if (lmin == g) {
            float nl = INF;
            #pragma unroll
            for (int q = 0; q < CAP / 32; q++) {
                if (v[q] == g) v[q] = INF;
                nl = fminf(nl, v[q]);
            }
            lmin = nl;
        }
    }
    // Compact slot-by-slot. Reads of slot q happen before writes (ballot is a
    // convergence point); write pos <= nc-1 < 32q <= read pos across slots.
    int nc = 0;
    #pragma unroll
    for (int q = 0; q < CAP / 32; q++) {
        int p = lane + 32 * q;
        unsigned long long e = (p < cnt) ? buf[p] : ~0ull;
        bool keep = (p < cnt) && (__uint_as_float((unsigned)(e >> 32)) <= g);
        unsigned m = __ballot_sync(FULLM, keep);
        if (keep) buf[nc + __popc(m & ((1u << lane) - 1u))] = e;
        nc += __popc(m);
    }
    __syncwarp();
    cnt = nc;
    thr = g;
    if (cnt > TRIG) {   // pathological ties: exact fallback
        unsigned long long gg = select_sorted(buf, cnt, KEEP, lane);
        cnt = KEEP;
        thr = __uint_as_float((unsigned)(gg >> 32));
    }
}

// Batched append of up to 4 values per lane: one bit-plane prefix (3 ballots),
// one rebuild check. base_lane = chunk_base + lane*4; indices +0..3.
__device__ __forceinline__ void append4(
    bool p0, bool p1, bool p2, bool p3,
    float s0, float s1, float s2, float s3, unsigned base_lane,
    unsigned long long* buf, int& cnt, float& thr, int lane)
{
    int np = (int)p0 + (int)p1 + (int)p2 + (int)p3;
    unsigned m0 = __ballot_sync(FULLM, np & 1);
    unsigned m1 = __ballot_sync(FULLM, np & 2);
    unsigned m2 = __ballot_sync(FULLM, np & 4);
    unsigned below = (1u << lane) - 1u;
    int off = cnt + __popc(m0 & below) + 2 * __popc(m1 & below)
                  + 4 * __popc(m2 & below);
    if (p0) buf[off++] = pack_key(s0, base_lane + 0u);
    if (p1) buf[off++] = pack_key(s1, base_lane + 1u);
    if (p2) buf[off++] = pack_key(s2, base_lane + 2u);
    if (p3) buf[off++] = pack_key(s3, base_lane + 3u);
    cnt += __popc(m0) + 2 * __popc(m1) + 4 * __popc(m2);
    if (cnt > TRIG) { __syncwarp(); rebuild32(buf, cnt, thr, lane); }
}

__global__ __launch_bounds__(96)
void nn_topk_kernel(const float* __restrict__ x,
                    const float* __restrict__ dlon,
                    const float* __restrict__ dlat,
                    float* __restrict__ out)
{
    // R9 layout: per-warp 8-slot x 512B rings; warp0 has a second ring (dlat).
    __shared__ float4 ringA[3][8][32];
    __shared__ float4 ringB[8][32];
    __shared__ unsigned long long sbuf[3][CAP];

    const int row  = blockIdx.x;
    const int warp = threadIdx.x >> 5;
    const int lane = threadIdx.x & 31;
    unsigned long long* buf = sbuf[warp];

    float thr = __int_as_float(0x7f800000);  // +inf until first rebuild
    int cnt = 0;

    const float* srcA = (warp == 2) ? (dlat + (size_t)row * S_DIM)
                                    : (dlon + (size_t)row * S_DIM);
    const float* srcB = dlat + (size_t)row * S_DIM;   // warp0 only

    constexpr int NIT = S_DIM / 128;   // 128 chunks of 128 elements

    #pragma unroll
    for (int p = 0; p < 7; ++p) {
        CP16(saddr(&ringA[warp][p][lane]), srcA + p * 128 + lane * 4);
        if (warp == 0)
            CP16(saddr(&ringB[p][lane]), srcB + p * 128 + lane * 4);
        CPCOMMIT();
    }

    if (warp == 0) {
        // ---- euclidean distance: scan squared values (monotone under sqrt) ----
        #pragma unroll 1
        for (int it = 0; it < NIT; ++it) {
            CPWAIT6();
            float4 a = ringA[0][it & 7][lane];
            float4 b = ringB[it & 7][lane];
            int nx = it + 7;
            if (nx < NIT) {
                CP16(saddr(&ringA[0][nx & 7][lane]), srcA + nx * 128 + lane * 4);
                CP16(saddr(&ringB[nx & 7][lane]),    srcB + nx * 128 + lane * 4);
            }
            CPCOMMIT();
            float s0 = fmaf(a.x, a.x, b.x * b.x);
            float s1 = fmaf(a.y, a.y, b.y * b.y);
            float s2 = fmaf(a.z, a.z, b.z * b.z);
            float s3 = fmaf(a.w, a.w, b.w * b.w);
            float mn = fminf(fminf(s0, s1), fminf(s2, s3));
            if (__any_sync(FULLM, mn <= thr)) {
                unsigned base = (unsigned)(it * 128) + (unsigned)lane * 4u;
                append4(s0 <= thr, s1 <= thr, s2 <= thr, s3 <= thr,
                        s0, s1, s2, s3, base, buf, cnt, thr, lane);
            }
        }
        // Re-key survivors with exact IEEE sqrt (order matches reference).
        __syncwarp();
        for (int p = lane; p < cnt; p += 32) {
            unsigned long long e = buf[p];
            float d = __fsqrt_rn(__uint_as_float((unsigned)(e >> 32)));
            buf[p] = pack_key(d, (unsigned)e);
        }
        __syncwarp();
        select_sorted(buf, cnt, NH, lane);   // buf[0..15] = final sorted keys

        if (lane < NH) {
            unsigned idx = (unsigned)buf[lane];
            out[OFF_IDIST + (size_t)row * NH + lane] = (float)idx;
        }
        __syncwarp();
        #pragma unroll
        for (int p = lane; p < B_DIM * NH; p += 32) {
            int b = p >> 4;
            int j = p & 15;
            unsigned idx = (unsigned)buf[j];
            out[OFF_XNEAR + (size_t)b * (T_DIM * NH) + (size_t)row * NH + j] =
                x[(size_t)b * S_DIM + idx];
        }
    } else {
        // ---- |d_lon| (warp 1) / |d_lat| (warp 2) ----
        #pragma unroll 1
        for (int it = 0; it < NIT; ++it) {
            CPWAIT6();
            float4 a = ringA[warp][it & 7][lane];
            int nx = it + 7;
            if (nx < NIT)
                CP16(saddr(&ringA[warp][nx & 7][lane]), srcA + nx * 128 + lane * 4);
            CPCOMMIT();
            float a0 = fabsf(a.x), a1 = fabsf(a.y), a2 = fabsf(a.z), a3 = fabsf(a.w);
            float mn = fminf(fminf(a0, a1), fminf(a2, a3));
            if (__any_sync(FULLM, mn <= thr)) {
                unsigned base = (unsigned)(it * 128) + (unsigned)lane * 4u;
                append4(a0 <= thr, a1 <= thr, a2 <= thr, a3 <= thr,
                        a0, a1, a2, a3, base, buf, cnt, thr, lane);
            }
        }
        __syncwarp();
        select_sorted(buf, cnt, NH, lane);
        const size_t obase = (warp == 1) ? OFF_ILON : OFF_ILAT;
        if (lane < NH) {
            unsigned idx = (unsigned)buf[lane];
            out[obase + (size_t)row * NH + lane] = (float)idx;
        }
    }
}

extern "C" void kernel_launch(void* const* d_in, const int* in_sizes, int n_in,
                              void* d_out, int out_size) {
    (void)in_sizes; (void)n_in; (void)out_size;
    const float* x    = (const float*)d_in[0];
    const float* dlon = (const float*)d_in[1];
    const float* dlat = (const float*)d_in[2];
    nn_topk_kernel<<<T_DIM, 96>>>(x, dlon, dlat, (float*)d_out);
}